// round 3
// baseline (speedup 1.0000x reference)
#include <cuda_runtime.h>

#define L 16384
#define THREADS 512
#define R 32

// XOR swizzle: makes every structured shared-memory pattern below bank-conflict-free.
// Bijection on [0, 16384).
__device__ __forceinline__ int ph(int i) { return i ^ ((i >> 5) & 31); }

// In-register FWHT butterflies over bits [0, NS) of the register index.
template <int NS>
__device__ __forceinline__ void fwht_stages(float v[R]) {
#pragma unroll
    for (int s = 0; s < NS; s++) {
        const int d = 1 << s;
#pragma unroll
        for (int r = 0; r < R; r++) {
            if ((r & d) == 0) {
                float a = v[r];
                float b = v[r + d];
                v[r] = a + b;
                v[r + d] = a - b;
            }
        }
    }
}

extern __shared__ float sh[];

// minBlocksPerMultiprocessor=2 forces regs<=64 so two 64KB-smem CTAs co-reside:
// occupancy fix for the 24.8%-occ / 23.6%-issue latency wall seen in Round 1.
__global__ void __launch_bounds__(THREADS, 2) ff_kernel(
    const float* __restrict__ x,
    const float* __restrict__ Bv,
    const float* __restrict__ Gv,
    const int* __restrict__ Pi,
    float* __restrict__ out)
{
    const int t = threadIdx.x;
    const int l = t & 31;       // lane
    const int w = t >> 5;       // warp, 0..15
    const int row = blockIdx.x;
    const float* xr = x + (size_t)row * L;
    float* outr = out + (size_t)row * L;

    float v[R];
    const int base = t * R;     // natural (P1) layout: i = t*32 + r

    // ---- load x * B (coalesced float4, consumed immediately to cap live regs) ----
#pragma unroll
    for (int c = 0; c < 8; c++) {
        float4 xv = *reinterpret_cast<const float4*>(xr + base + c * 4);
        float4 bv = *reinterpret_cast<const float4*>(Bv + base + c * 4);
        v[c * 4 + 0] = xv.x * bv.x;
        v[c * 4 + 1] = xv.y * bv.y;
        v[c * 4 + 2] = xv.z * bv.z;
        v[c * 4 + 3] = xv.w * bv.w;
    }

    // ================= FWHT #1 =================
    // P1: bits 0-4 in registers.
    // NOTE: ph(base + r) == base + (r ^ l)  (base = t*32, so (i>>5)&31 == l).
    // (Round 2's "ph(base)+r" was WRONG and out-of-bounds; this form is exact.)
    fwht_stages<5>(v);
#pragma unroll
    for (int r = 0; r < R; r++) sh[base + (r ^ l)] = v[r];
    __syncthreads();

    // P2: bits 5-9 in registers.  i = w*1024 + r*32 + l
#pragma unroll
    for (int r = 0; r < R; r++) v[r] = sh[ph(w * 1024 + r * 32 + l)];
    fwht_stages<5>(v);
    // each thread writes back exactly the addresses it read: no sync needed in between
#pragma unroll
    for (int r = 0; r < R; r++) sh[ph(w * 1024 + r * 32 + l)] = v[r];
    __syncthreads();

    // P3: bits 10-13 in registers (bit 9 rides along as passenger).
    // i = (r&15)*1024 + (r>>4)*512 + w*32 + l
#pragma unroll
    for (int r = 0; r < R; r++)
        v[r] = sh[ph((r & 15) * 1024 + (r >> 4) * 512 + w * 32 + l)];
    fwht_stages<4>(v);
#pragma unroll
    for (int r = 0; r < R; r++)
        sh[ph((r & 15) * 1024 + (r >> 4) * 512 + w * 32 + l)] = v[r];
    __syncthreads();

    // ---- permutation gather + gain + combined scale (1/sqrt(N))^2 = 1/16384 ----
    constexpr float SC = 1.0f / 16384.0f;
#pragma unroll
    for (int c = 0; c < 8; c++) {
        int4   p = *reinterpret_cast<const int4*>(Pi + base + c * 4);
        float4 g = *reinterpret_cast<const float4*>(Gv + base + c * 4);
        v[c * 4 + 0] = sh[ph(p.x)] * (g.x * SC);
        v[c * 4 + 1] = sh[ph(p.y)] * (g.y * SC);
        v[c * 4 + 2] = sh[ph(p.z)] * (g.z * SC);
        v[c * 4 + 3] = sh[ph(p.w)] * (g.w * SC);
    }

    // ================= FWHT #2 =================
    // P1 (gather already delivered natural layout: regs = bits 0-4)
    fwht_stages<5>(v);
    __syncthreads();   // all gathers of y1 complete before overwriting sh
#pragma unroll
    for (int r = 0; r < R; r++) sh[base + (r ^ l)] = v[r];
    __syncthreads();

    // P2
#pragma unroll
    for (int r = 0; r < R; r++) v[r] = sh[ph(w * 1024 + r * 32 + l)];
    fwht_stages<5>(v);
#pragma unroll
    for (int r = 0; r < R; r++) sh[ph(w * 1024 + r * 32 + l)] = v[r];
    __syncthreads();

    // P3
#pragma unroll
    for (int r = 0; r < R; r++)
        v[r] = sh[ph((r & 15) * 1024 + (r >> 4) * 512 + w * 32 + l)];
    fwht_stages<4>(v);

    // ---- final store: P3 layout is lane-consecutive -> coalesced STG.32 ----
#pragma unroll
    for (int r = 0; r < R; r++)
        outr[(r & 15) * 1024 + (r >> 4) * 512 + w * 32 + l] = v[r];
}

extern "C" void kernel_launch(void* const* d_in, const int* in_sizes, int n_in,
                              void* d_out, int out_size)
{
    const float* x  = (const float*)d_in[0];
    const float* B  = (const float*)d_in[1];
    const float* G  = (const float*)d_in[2];
    const int*   Pi = (const int*)d_in[3];
    float* out = (float*)d_out;

    const int rows = in_sizes[0] / L;   // 4096

    // 64 KB dynamic shared per CTA (above the 48 KB static limit): opt in every call
    // (idempotent, deterministic, not a stream op — safe under graph capture).
    cudaFuncSetAttribute(ff_kernel, cudaFuncAttributeMaxDynamicSharedMemorySize, L * (int)sizeof(float));

    ff_kernel<<<rows, THREADS, L * sizeof(float)>>>(x, B, G, Pi, out);
}

// round 5
// speedup vs baseline: 1.2887x; 1.2887x over previous
#include <cuda_runtime.h>

#define L 16384
#define THREADS 1024
#define R 16

// Swizzle for the R=16 geometry: XOR bits [4:9) of the element index into the
// bank bits. Bijection on [0, 16384) (bits 4..8 untouched -> invertible).
__device__ __forceinline__ int ph(int i) { return i ^ ((i >> 4) & 31); }

// In-register FWHT butterflies over bits [0, NS) of the register index.
template <int NS>
__device__ __forceinline__ void fwht_stages(float v[R]) {
#pragma unroll
    for (int s = 0; s < NS; s++) {
        const int d = 1 << s;
#pragma unroll
        for (int r = 0; r < R; r++) {
            if ((r & d) == 0) {
                float a = v[r];
                float b = v[r + d];
                v[r] = a + b;
                v[r + d] = a - b;
            }
        }
    }
}

extern __shared__ float sh[];

// 1024 threads, 16 elements each. Reg need ~40 << 64 cap: no spills (the R3
// lesson: 32 elem/thread + 2 CTAs = forced spill, +347MB DRAM traffic).
__global__ void __launch_bounds__(THREADS, 1) ff_kernel(
    const float* __restrict__ x,
    const float* __restrict__ Bv,
    const float* __restrict__ Gv,
    const int* __restrict__ Pi,
    float* __restrict__ out)
{
    const int t = threadIdx.x;
    const int row = blockIdx.x;
    const float* xr = x + (size_t)row * L;
    float* outr = out + (size_t)row * L;

    // Pass element maps (each pass puts 4 element-index bits in regs):
    //  P1: i = t*16 + r                      (bits 0-3)
    //  P2: i = q*256 + r*16 + s, t=q*16+s    (bits 4-7)
    //  P3: i = u*4096 + r*256 + m, t=u*256+m (bits 8-11)
    //  P4: i = (r&3)*4096 + (r>>2)*1024 + t  (bits 12-13; r>>2 = passengers)
    const int q = t >> 4, s = t & 15;
    const int u = t >> 8, m = t & 255;

    float v[R];
    const int base = t * R;

    // ---- load x * B (4x float4, coalesced) ----
#pragma unroll
    for (int c = 0; c < 4; c++) {
        float4 xv = *reinterpret_cast<const float4*>(xr + base + c * 4);
        float4 bv = *reinterpret_cast<const float4*>(Bv + base + c * 4);
        v[c * 4 + 0] = xv.x * bv.x;
        v[c * 4 + 1] = xv.y * bv.y;
        v[c * 4 + 2] = xv.z * bv.z;
        v[c * 4 + 3] = xv.w * bv.w;
    }

    // ================= FWHT #1 =================
    // P1 (bits 0-3). Store through ph() directly — the R2/R4 "simplified"
    // address algebra was wrong both times; ph(base+r) is the ground truth.
    // Bank = (((t&1)<<4)|r) ^ lane: injective per lane -> conflict-free.
    fwht_stages<4>(v);
#pragma unroll
    for (int r = 0; r < R; r++) sh[ph(base + r)] = v[r];
    __syncthreads();

    // P2 (bits 4-7)
#pragma unroll
    for (int r = 0; r < R; r++) v[r] = sh[ph(q * 256 + r * 16 + s)];
    fwht_stages<4>(v);
#pragma unroll
    for (int r = 0; r < R; r++) sh[ph(q * 256 + r * 16 + s)] = v[r];
    __syncthreads();

    // P3 (bits 8-11)
#pragma unroll
    for (int r = 0; r < R; r++) v[r] = sh[ph(u * 4096 + r * 256 + m)];
    fwht_stages<4>(v);
#pragma unroll
    for (int r = 0; r < R; r++) sh[ph(u * 4096 + r * 256 + m)] = v[r];
    __syncthreads();

    // P4 (bits 12-13; 2-stage FWHT, 4 passenger groups)
#pragma unroll
    for (int r = 0; r < R; r++)
        v[r] = sh[ph((r & 3) * 4096 + (r >> 2) * 1024 + t)];
#pragma unroll
    for (int g = 0; g < 4; g++) {
        float a0 = v[g * 4 + 0], a1 = v[g * 4 + 1], a2 = v[g * 4 + 2], a3 = v[g * 4 + 3];
        float b0 = a0 + a1, b1 = a0 - a1, b2 = a2 + a3, b3 = a2 - a3;
        v[g * 4 + 0] = b0 + b2; v[g * 4 + 2] = b0 - b2;
        v[g * 4 + 1] = b1 + b3; v[g * 4 + 3] = b1 - b3;
    }
#pragma unroll
    for (int r = 0; r < R; r++)
        sh[ph((r & 3) * 4096 + (r >> 2) * 1024 + t)] = v[r];
    __syncthreads();

    // ---- permutation gather + gain + combined scale (1/sqrt(N))^2 ----
    constexpr float SC = 1.0f / 16384.0f;
#pragma unroll
    for (int c = 0; c < 4; c++) {
        int4   p = *reinterpret_cast<const int4*>(Pi + base + c * 4);
        float4 g = *reinterpret_cast<const float4*>(Gv + base + c * 4);
        v[c * 4 + 0] = sh[ph(p.x)] * (g.x * SC);
        v[c * 4 + 1] = sh[ph(p.y)] * (g.y * SC);
        v[c * 4 + 2] = sh[ph(p.z)] * (g.z * SC);
        v[c * 4 + 3] = sh[ph(p.w)] * (g.w * SC);
    }

    // ================= FWHT #2 =================
    // P1 (gather delivered natural layout: regs = bits 0-3)
    fwht_stages<4>(v);
    __syncthreads();   // all gathers complete before overwriting sh
#pragma unroll
    for (int r = 0; r < R; r++) sh[ph(base + r)] = v[r];
    __syncthreads();

    // P2
#pragma unroll
    for (int r = 0; r < R; r++) v[r] = sh[ph(q * 256 + r * 16 + s)];
    fwht_stages<4>(v);
#pragma unroll
    for (int r = 0; r < R; r++) sh[ph(q * 256 + r * 16 + s)] = v[r];
    __syncthreads();

    // P3
#pragma unroll
    for (int r = 0; r < R; r++) v[r] = sh[ph(u * 4096 + r * 256 + m)];
    fwht_stages<4>(v);
#pragma unroll
    for (int r = 0; r < R; r++) sh[ph(u * 4096 + r * 256 + m)] = v[r];
    __syncthreads();

    // P4 + final store (coalesced STG.32: consecutive lanes -> consecutive addrs)
#pragma unroll
    for (int r = 0; r < R; r++)
        v[r] = sh[ph((r & 3) * 4096 + (r >> 2) * 1024 + t)];
#pragma unroll
    for (int g = 0; g < 4; g++) {
        float a0 = v[g * 4 + 0], a1 = v[g * 4 + 1], a2 = v[g * 4 + 2], a3 = v[g * 4 + 3];
        float b0 = a0 + a1, b1 = a0 - a1, b2 = a2 + a3, b3 = a2 - a3;
        v[g * 4 + 0] = b0 + b2; v[g * 4 + 2] = b0 - b2;
        v[g * 4 + 1] = b1 + b3; v[g * 4 + 3] = b1 - b3;
    }
#pragma unroll
    for (int r = 0; r < R; r++)
        outr[(r & 3) * 4096 + (r >> 2) * 1024 + t] = v[r];
}

extern "C" void kernel_launch(void* const* d_in, const int* in_sizes, int n_in,
                              void* d_out, int out_size)
{
    const float* x  = (const float*)d_in[0];
    const float* B  = (const float*)d_in[1];
    const float* G  = (const float*)d_in[2];
    const int*   Pi = (const int*)d_in[3];
    float* out = (float*)d_out;

    const int rows = in_sizes[0] / L;   // 4096

    cudaFuncSetAttribute(ff_kernel, cudaFuncAttributeMaxDynamicSharedMemorySize, L * (int)sizeof(float));

    ff_kernel<<<rows, THREADS, L * sizeof(float)>>>(x, B, G, Pi, out);
}

// round 6
// speedup vs baseline: 1.2988x; 1.0078x over previous
#include <cuda_runtime.h>

#define L 16384
#define THREADS 1024
#define R 16

// Swizzle for the R=16 geometry: XOR bits [4:9) of the element index into the
// bank bits. Bijection on [0, 16384) (bits 4..8 untouched -> invertible).
__device__ __forceinline__ int ph(int i) { return i ^ ((i >> 4) & 31); }

// Named barrier over an aligned 256-thread (8-warp) group.
__device__ __forceinline__ void bar256(int gid) {
    asm volatile("bar.sync %0, %1;" :: "r"(gid + 1), "r"(256) : "memory");
}

// In-register FWHT butterflies over bits [0, NS) of the register index.
template <int NS>
__device__ __forceinline__ void fwht_stages(float v[R]) {
#pragma unroll
    for (int s = 0; s < NS; s++) {
        const int d = 1 << s;
#pragma unroll
        for (int r = 0; r < R; r++) {
            if ((r & d) == 0) {
                float a = v[r];
                float b = v[r + d];
                v[r] = a + b;
                v[r + d] = a - b;
            }
        }
    }
}

extern __shared__ float sh[];

__global__ void __launch_bounds__(THREADS, 1) ff_kernel(
    const float* __restrict__ x,
    const float* __restrict__ Bv,
    const float* __restrict__ Gv,
    const int* __restrict__ Pi,
    float* __restrict__ out)
{
    const int t = threadIdx.x;
    const int row = blockIdx.x;
    const float* xr = x + (size_t)row * L;
    float* outr = out + (size_t)row * L;

    // Pass element maps (each pass puts 4 element-index bits in regs):
    //  P1: i = t*16 + r                      (bits 0-3)
    //  P2: i = q*256 + r*16 + s, t=q*16+s    (bits 4-7)   exchange: 16-thread groups (intra-warp)
    //  P3: i = u*4096 + r*256 + m, t=u*256+m (bits 8-11)  exchange: 256-thread groups
    //  P4: i = (r&3)*4096 + (r>>2)*1024 + t  (bits 12-13) exchange: whole CTA
    const int q = t >> 4, s = t & 15;
    const int u = t >> 8, m = t & 255;

    float v[R];
    const int base = t * R;

    // ---- load x * B (4x float4, coalesced) ----
#pragma unroll
    for (int c = 0; c < 4; c++) {
        float4 xv = *reinterpret_cast<const float4*>(xr + base + c * 4);
        float4 bv = *reinterpret_cast<const float4*>(Bv + base + c * 4);
        v[c * 4 + 0] = xv.x * bv.x;
        v[c * 4 + 1] = xv.y * bv.y;
        v[c * 4 + 2] = xv.z * bv.z;
        v[c * 4 + 3] = xv.w * bv.w;
    }

    // ================= FWHT #1 =================
    // P1 (bits 0-3)
    fwht_stages<4>(v);
#pragma unroll
    for (int r = 0; r < R; r++) sh[ph(base + r)] = v[r];
    __syncwarp();                       // P1->P2 exchange is intra-warp

    // P2 (bits 4-7)
#pragma unroll
    for (int r = 0; r < R; r++) v[r] = sh[ph(q * 256 + r * 16 + s)];
    fwht_stages<4>(v);
#pragma unroll
    for (int r = 0; r < R; r++) sh[ph(q * 256 + r * 16 + s)] = v[r];
    bar256(u);                          // P2->P3 exchange is within 256-thread group

    // P3 (bits 8-11)
#pragma unroll
    for (int r = 0; r < R; r++) v[r] = sh[ph(u * 4096 + r * 256 + m)];
    fwht_stages<4>(v);
#pragma unroll
    for (int r = 0; r < R; r++) sh[ph(u * 4096 + r * 256 + m)] = v[r];
    __syncthreads();                    // P3->P4 crosses the CTA

    // P4 (bits 12-13; 2-stage FWHT, 4 passenger groups)
#pragma unroll
    for (int r = 0; r < R; r++)
        v[r] = sh[ph((r & 3) * 4096 + (r >> 2) * 1024 + t)];
#pragma unroll
    for (int g = 0; g < 4; g++) {
        float a0 = v[g * 4 + 0], a1 = v[g * 4 + 1], a2 = v[g * 4 + 2], a3 = v[g * 4 + 3];
        float b0 = a0 + a1, b1 = a0 - a1, b2 = a2 + a3, b3 = a2 - a3;
        v[g * 4 + 0] = b0 + b2; v[g * 4 + 2] = b0 - b2;
        v[g * 4 + 1] = b1 + b3; v[g * 4 + 3] = b1 - b3;
    }
#pragma unroll
    for (int r = 0; r < R; r++)
        sh[ph((r & 3) * 4096 + (r >> 2) * 1024 + t)] = v[r];
    __syncthreads();                    // gather reads arbitrary positions

    // ---- permutation gather + gain + combined scale (1/sqrt(N))^2 ----
    constexpr float SC = 1.0f / 16384.0f;
#pragma unroll
    for (int c = 0; c < 4; c++) {
        int4   p = *reinterpret_cast<const int4*>(Pi + base + c * 4);
        float4 g = *reinterpret_cast<const float4*>(Gv + base + c * 4);
        v[c * 4 + 0] = sh[ph(p.x)] * (g.x * SC);
        v[c * 4 + 1] = sh[ph(p.y)] * (g.y * SC);
        v[c * 4 + 2] = sh[ph(p.z)] * (g.z * SC);
        v[c * 4 + 3] = sh[ph(p.w)] * (g.w * SC);
    }

    // ================= FWHT #2 =================
    // P1 (gather delivered natural layout: regs = bits 0-3)
    fwht_stages<4>(v);
    __syncthreads();                    // all gathers complete before overwriting sh
#pragma unroll
    for (int r = 0; r < R; r++) sh[ph(base + r)] = v[r];
    __syncwarp();

    // P2
#pragma unroll
    for (int r = 0; r < R; r++) v[r] = sh[ph(q * 256 + r * 16 + s)];
    fwht_stages<4>(v);
#pragma unroll
    for (int r = 0; r < R; r++) sh[ph(q * 256 + r * 16 + s)] = v[r];
    bar256(u);

    // P3
#pragma unroll
    for (int r = 0; r < R; r++) v[r] = sh[ph(u * 4096 + r * 256 + m)];
    fwht_stages<4>(v);
#pragma unroll
    for (int r = 0; r < R; r++) sh[ph(u * 4096 + r * 256 + m)] = v[r];
    __syncthreads();

    // P4 + final store (coalesced STG.32: consecutive lanes -> consecutive addrs)
#pragma unroll
    for (int r = 0; r < R; r++)
        v[r] = sh[ph((r & 3) * 4096 + (r >> 2) * 1024 + t)];
#pragma unroll
    for (int g = 0; g < 4; g++) {
        float a0 = v[g * 4 + 0], a1 = v[g * 4 + 1], a2 = v[g * 4 + 2], a3 = v[g * 4 + 3];
        float b0 = a0 + a1, b1 = a0 - a1, b2 = a2 + a3, b3 = a2 - a3;
        v[g * 4 + 0] = b0 + b2; v[g * 4 + 2] = b0 - b2;
        v[g * 4 + 1] = b1 + b3; v[g * 4 + 3] = b1 - b3;
    }
#pragma unroll
    for (int r = 0; r < R; r++)
        outr[(r & 3) * 4096 + (r >> 2) * 1024 + t] = v[r];
}

extern "C" void kernel_launch(void* const* d_in, const int* in_sizes, int n_in,
                              void* d_out, int out_size)
{
    const float* x  = (const float*)d_in[0];
    const float* B  = (const float*)d_in[1];
    const float* G  = (const float*)d_in[2];
    const int*   Pi = (const int*)d_in[3];
    float* out = (float*)d_out;

    const int rows = in_sizes[0] / L;   // 4096

    cudaFuncSetAttribute(ff_kernel, cudaFuncAttributeMaxDynamicSharedMemorySize, L * (int)sizeof(float));

    ff_kernel<<<rows, THREADS, L * sizeof(float)>>>(x, B, G, Pi, out);
}